// round 12
// baseline (speedup 1.0000x reference)
#include <cuda_runtime.h>
#include <cuda_fp16.h>
#include <cstdint>

#define BB 2
#define TT 2048
#define DD 1024
#define HH 16
#define DH 64
#define VV 32000
#define NTOK (BB*TT)   /* 4096 */

typedef __half f16;

// ---------------- scratch (device globals; no allocations allowed) -------------
__device__ float g_gains[DD];
__device__ f16 g_xrf[NTOK*DD];                  // single fp16 (r path A)
__device__ f16 g_xkh[NTOK*DD], g_xkl[NTOK*DD];  // 2-split (k path A)
__device__ f16 g_xvf[NTOK*DD];                  // single fp16 (v path A)
__device__ f16 g_of [NTOK*DD];                  // flash out, single fp16
__device__ f16 g_wrh[DD*DD];                    // single fp16 weights (r)
__device__ f16 g_wkh[DD*DD], g_wkl[DD*DD];      // 2-split weights (k)
__device__ f16 g_wvh[DD*DD];                    // single (v)
__device__ f16 g_woh[DD*DD];                    // single (out)
__device__ f16   g_qf  [NTOK*DD];               // fp16 Q = r * QSCALE
__device__ float g_gate[NTOK*DD];               // fp32 sigmoid(r)
__device__ f16  g_kb[NTOK*DD];                  // spikes {0,1} exact
__device__ f16  g_vth[BB*HH*DH*TT];             // V^T [b][h][dh][t], single fp16

#define QSCALE (0.125f * 1.44269504f)

__device__ __forceinline__ uint32_t pack_h2(float a, float b) {
    __half2 t = __floats2half2_rn(a, b);
    return *(uint32_t*)&t;
}
__device__ __forceinline__ void split_pack_h(float a, float b, uint32_t& hi, uint32_t& lo) {
    f16 ha = __float2half_rn(a), hb = __float2half_rn(b);
    hi = ((uint32_t)*(uint16_t*)&hb << 16) | (uint32_t)*(uint16_t*)&ha;
    lo = pack_h2(a - __half2float(ha), b - __half2float(hb));
}
__device__ __forceinline__ uint32_t smem_u32(const void* p) {
    return (uint32_t)__cvta_generic_to_shared(p);
}
__device__ __forceinline__ void cpa16(uint32_t dst, const void* src) {
    asm volatile("cp.async.cg.shared.global [%0], [%1], 16;\n" :: "r"(dst), "l"(src));
}
__device__ __forceinline__ void cp_commit() { asm volatile("cp.async.commit_group;\n"); }
template <int N> __device__ __forceinline__ void cp_wait() {
    asm volatile("cp.async.wait_group %0;\n" :: "n"(N));
}
__device__ __forceinline__ void ldsm4(uint32_t r[4], uint32_t addr) {
    asm volatile("ldmatrix.sync.aligned.m8n8.x4.shared.b16 {%0,%1,%2,%3}, [%4];"
        : "=r"(r[0]), "=r"(r[1]), "=r"(r[2]), "=r"(r[3]) : "r"(addr));
}
__device__ __forceinline__ void mma_f16(float c[4], uint32_t a0, uint32_t a1,
                                        uint32_t a2, uint32_t a3,
                                        uint32_t b0, uint32_t b1) {
    asm volatile(
        "mma.sync.aligned.m16n8k16.row.col.f32.f16.f16.f32 "
        "{%0,%1,%2,%3}, {%4,%5,%6,%7}, {%8,%9}, {%0,%1,%2,%3};\n"
        : "+f"(c[0]), "+f"(c[1]), "+f"(c[2]), "+f"(c[3])
        : "r"(a0), "r"(a1), "r"(a2), "r"(a3), "r"(b0), "r"(b1));
}

// half2 exp2 via magic rounding + deg-3 poly (no MUFU). Input lanes in [-14, 15].
__device__ __forceinline__ uint32_t exp2h2(uint32_t s2u) {
    __half2 s = *(__half2*)&s2u;
    s = __hmax2(s, __float2half2_rn(-14.0f));
    const __half2 magic = __float2half2_rn(1536.0f);
    __half2 u = __hadd2(s, magic);
    __half2 f = __hsub2(s, __hsub2(u, magic));
    __half2 p = __hfma2(__hfma2(__hfma2(__float2half2_rn(0.05550411f), f,
                                        __float2half2_rn(0.24022651f)), f,
                                __float2half2_rn(0.69314718f)), f,
                        __float2half2_rn(1.0f));
    uint32_t eb = ((*(uint32_t*)&u) - 0x65F165F1u) << 10;
    __half2 r = __hmul2(p, *(__half2*)&eb);
    return *(uint32_t*)&r;
}

// ---------------- fused kWTA + weight split -------------------------------------
#define KWTA_SMEM ((VV + 1024 + 8) * 4)
__global__ void kwta_split_kernel(const int* __restrict__ tok,
                                  const float* __restrict__ Wr, const float* __restrict__ Wk,
                                  const float* __restrict__ Wv, const float* __restrict__ Wo) {
    int tid = threadIdx.x;
    if (blockIdx.x != 0) {
        int base = (blockIdx.x - 1) * blockDim.x + tid;
        for (int i = base; i < DD * DD / 2; i += 128 * blockDim.x) {
            float2 a;
            uint32_t h, l;
            a = ((const float2*)Wr)[i];
            ((uint32_t*)g_wrh)[i] = pack_h2(a.x, a.y);
            a = ((const float2*)Wk)[i];
            split_pack_h(a.x, a.y, h, l);
            ((uint32_t*)g_wkh)[i] = h; ((uint32_t*)g_wkl)[i] = l;
            a = ((const float2*)Wv)[i];
            ((uint32_t*)g_wvh)[i] = pack_h2(a.x, a.y);
            a = ((const float2*)Wo)[i];
            ((uint32_t*)g_woh)[i] = pack_h2(a.x, a.y);
        }
        return;
    }
    extern __shared__ int sh[];
    int* hist = sh;
    int* red  = sh + VV;
    int* sel  = sh + VV + 1024;
    for (int i = tid; i < VV; i += 1024) hist[i] = 0;
    __syncthreads();
    for (int i = tid; i < NTOK; i += 1024) atomicAdd(&hist[tok[i]], 1);
    __syncthreads();
    for (int p = 0; p < 5; p++) {
        int best = -1;
        for (int v = tid; v < VV; v += 1024) {
            bool skip = false;
            for (int i = 0; i < p; i++) if (sel[i] == v) skip = true;
            if (!skip) {
                int key = (hist[v] << 15) | (32767 - v);
                if (key > best) best = key;
            }
        }
        red[tid] = best;
        __syncthreads();
        for (int off = 512; off > 0; off >>= 1) {
            if (tid < off) { int o = red[tid + off]; if (o > red[tid]) red[tid] = o; }
            __syncthreads();
        }
        if (tid == 0) sel[p] = 32767 - (red[0] & 32767);
        __syncthreads();
    }
    float g = (hist[tid] > 0) ? 0.6f : 1.0f;
    for (int i = 0; i < 5; i++) if (sel[i] == tid) g = 1.5f;
    g_gains[tid] = g;
}

// ---------------- token-shift time mixing ---------------------------------------
__global__ void mix_kernel(const float* __restrict__ x,
                           const float* __restrict__ tmk,
                           const float* __restrict__ tmv,
                           const float* __restrict__ tmr) {
    int i = blockIdx.x * blockDim.x + threadIdx.x;
    if (i >= NTOK * DD / 2) return;
    int dp = i & (DD / 2 - 1);
    int t = (i >> 9) & (TT - 1);
    float2 xc = ((const float2*)x)[i];
    float2 xp = (t == 0) ? make_float2(0.f, 0.f) : ((const float2*)x)[i - DD / 2];
    int d = dp * 2;
    float g0 = g_gains[d], g1 = g_gains[d + 1];
    float2 tr = ((const float2*)tmr)[dp];
    float2 tk = ((const float2*)tmk)[dp];
    float2 tv = ((const float2*)tmv)[dp];
    float m0, m1;
    m0 = tr.x * g0; m1 = tr.y * g1;
    ((uint32_t*)g_xrf)[i] = pack_h2(m0 * xc.x + (1.f - m0) * xp.x,
                                    m1 * xc.y + (1.f - m1) * xp.y);
    uint32_t h, l;
    m0 = tk.x * g0; m1 = tk.y * g1;
    split_pack_h(m0 * xc.x + (1.f - m0) * xp.x, m1 * xc.y + (1.f - m1) * xp.y, h, l);
    ((uint32_t*)g_xkh)[i] = h; ((uint32_t*)g_xkl)[i] = l;
    m0 = tv.x * g0; m1 = tv.y * g1;
    ((uint32_t*)g_xvf)[i] = pack_h2(m0 * xc.x + (1.f - m0) * xp.x,
                                    m1 * xc.y + (1.f - m1) * xp.y);
}

// ---------------- mma GEMM core: 3-stage, single-sync, XOR-swizzled -------------
#define GEMM_SMEM   (3*4*128*64)   /* 98304 B (k mode) */
#define GEMM_SMEM_S (3*2*128*64)   /* 49152 B (single mode) */

template <int KM>
__device__ __forceinline__ void gemm_core(
        const f16* __restrict__ A0, const f16* __restrict__ A1,
        const f16* __restrict__ W0, const f16* __restrict__ W1,
        int n0, int d0, uint16_t* sm, float acc[4][4][4]) {
    const int NARR = KM ? 4 : 2;
    int t = threadIdx.x;
    int lane = t & 31, warp = t >> 5;
    int wm = (warp & 1) * 64, wn = (warp >> 1) * 32;
    uint32_t sb = smem_u32(sm);

    int aRowOff = (lane & 7) + ((lane & 8) ? 8 : 0);
    int aChunk  = lane >> 4;
    int wRowOff = (lane & 7) + ((lane >> 4) & 1) * 8;
    int wChunk  = (lane >> 3) & 1;

    const f16* baseP[4];
    if (KM) {
        baseP[0] = A0 + (size_t)n0 * DD; baseP[1] = A1 + (size_t)n0 * DD;
        baseP[2] = W0 + (size_t)d0 * DD; baseP[3] = W1 + (size_t)d0 * DD;
    } else {
        baseP[0] = A0 + (size_t)n0 * DD; baseP[1] = W0 + (size_t)d0 * DD;
        baseP[2] = nullptr; baseP[3] = nullptr;
    }

    auto stage_load = [&](int st, int k0) {
        #pragma unroll
        for (int i = 0; i < 2 * NARR; i++) {
            const int arr = i >> 1;
            int rc = t + (i & 1) * 256;
            int row = rc >> 2, c = rc & 3;
            const f16* src = baseP[arr] + (size_t)row * DD + k0 + c * 8;
            int phys = c ^ ((row >> 1) & 3);
            uint32_t dst = sb + (uint32_t)(st * NARR * 8192 + arr * 8192 + row * 64 + phys * 16);
            cpa16(dst, src);
        }
        cp_commit();
    };

    stage_load(0, 0);
    stage_load(1, 32);
    for (int it = 0; it < 32; it++) {
        if (it == 31) cp_wait<0>(); else cp_wait<1>();
        __syncthreads();
        if (it < 30) stage_load((it + 2) % 3, (it + 2) * 32);

        int st = it % 3;
        uint32_t base = sb + (uint32_t)(st * NARR * 8192);
        uint32_t bA0 = base;
        uint32_t bA1 = base + 8192;
        uint32_t bW0 = base + (KM ? 16384 : 8192);
        uint32_t bW1 = base + 24576;

        #pragma unroll
        for (int ks = 0; ks < 2; ks++) {
            int kc8 = ks * 2;
            uint32_t ah[4][4], al[4][4];
            #pragma unroll
            for (int mi = 0; mi < 4; mi++) {
                int row = wm + mi * 16 + aRowOff;
                int ph = (kc8 + aChunk) ^ ((row >> 1) & 3);
                uint32_t off = (uint32_t)(row * 64 + ph * 16);
                ldsm4(ah[mi], bA0 + off);
                if (KM) ldsm4(al[mi], bA1 + off);
            }
            uint32_t bh[4][2], bl[4][2];
            #pragma unroll
            for (int pair = 0; pair < 2; pair++) {
                int row = wn + pair * 16 + wRowOff;
                int ph = (kc8 + wChunk) ^ ((row >> 1) & 3);
                uint32_t off = (uint32_t)(row * 64 + ph * 16);
                uint32_t qh[4];
                ldsm4(qh, bW0 + off);
                bh[pair * 2][0] = qh[0]; bh[pair * 2][1] = qh[1];
                bh[pair * 2 + 1][0] = qh[2]; bh[pair * 2 + 1][1] = qh[3];
                if (KM) {
                    uint32_t ql[4];
                    ldsm4(ql, bW1 + off);
                    bl[pair * 2][0] = ql[0]; bl[pair * 2][1] = ql[1];
                    bl[pair * 2 + 1][0] = ql[2]; bl[pair * 2 + 1][1] = ql[3];
                }
            }
            #pragma unroll
            for (int ni = 0; ni < 4; ni++)
                #pragma unroll
                for (int mi = 0; mi < 4; mi++) {
                    mma_f16(acc[mi][ni], ah[mi][0], ah[mi][1], ah[mi][2], ah[mi][3],
                            bh[ni][0], bh[ni][1]);
                    if (KM) {
                        mma_f16(acc[mi][ni], ah[mi][0], ah[mi][1], ah[mi][2], ah[mi][3],
                                bl[ni][0], bl[ni][1]);
                        mma_f16(acc[mi][ni], al[mi][0], al[mi][1], al[mi][2], al[mi][3],
                                bh[ni][0], bh[ni][1]);
                    }
                }
        }
    }
}

// ---------------- fused projection GEMMs (z: 0=k spike, 1=r, 2=v transposed) ----
__global__ void __launch_bounds__(256, 2) proj_gemm_kernel() {
    extern __shared__ uint16_t sm[];
    int mode = blockIdx.z;
    int n0 = blockIdx.y * 128, d0 = blockIdx.x * 128;

    float acc[4][4][4];
    #pragma unroll
    for (int i = 0; i < 4; i++)
        #pragma unroll
        for (int j = 0; j < 4; j++)
            #pragma unroll
            for (int q = 0; q < 4; q++) acc[i][j][q] = 0.0f;

    if (mode == 0)      gemm_core<1>(g_xkh, g_xkl, g_wkh, g_wkl, n0, d0, sm, acc);
    else if (mode == 1) gemm_core<0>(g_xrf, nullptr, g_wrh, nullptr, n0, d0, sm, acc);
    else                gemm_core<0>(g_xvf, nullptr, g_wvh, nullptr, n0, d0, sm, acc);

    int tid = threadIdx.x;
    int lane = tid & 31, warp = tid >> 5;
    int g = lane >> 2, t4 = lane & 3;
    int wm = (warp & 1) * 64, wn = (warp >> 1) * 32;

    if (mode == 1) {
        #pragma unroll
        for (int mi = 0; mi < 4; mi++)
            #pragma unroll
            for (int ni = 0; ni < 4; ni++) {
                int r = n0 + wm + mi * 16 + g;
                int col = d0 + wn + ni * 8 + t4 * 2;
                float v0 = acc[mi][ni][0], v1 = acc[mi][ni][1];
                float v2 = acc[mi][ni][2], v3 = acc[mi][ni][3];
                *(uint32_t*)&g_qf[(size_t)r * DD + col]       = pack_h2(v0 * QSCALE, v1 * QSCALE);
                *(uint32_t*)&g_qf[(size_t)(r + 8) * DD + col] = pack_h2(v2 * QSCALE, v3 * QSCALE);
                *(float2*)&g_gate[(size_t)r * DD + col] =
                    make_float2(1.f / (1.f + __expf(-v0)), 1.f / (1.f + __expf(-v1)));
                *(float2*)&g_gate[(size_t)(r + 8) * DD + col] =
                    make_float2(1.f / (1.f + __expf(-v2)), 1.f / (1.f + __expf(-v3)));
            }
    } else if (mode == 0) {
        #pragma unroll
        for (int mi = 0; mi < 4; mi++)
            #pragma unroll
            for (int ni = 0; ni < 4; ni++) {
                int r = n0 + wm + mi * 16 + g;
                int col = d0 + wn + ni * 8 + t4 * 2;
                *(uint32_t*)&g_kb[(size_t)r * DD + col] =
                    pack_h2(acc[mi][ni][0] > 0.5f ? 1.0f : 0.0f,
                            acc[mi][ni][1] > 0.5f ? 1.0f : 0.0f);
                *(uint32_t*)&g_kb[(size_t)(r + 8) * DD + col] =
                    pack_h2(acc[mi][ni][2] > 0.5f ? 1.0f : 0.0f,
                            acc[mi][ni][3] > 0.5f ? 1.0f : 0.0f);
            }
    } else {
        // V: smem transpose -> coalesced [b][h][dh][t] single-fp16 stores
        uint16_t* st = sm;
        int c = tid >> 1;
        int tstart = (tid & 1) * 64;
        int bbatch = n0 >> 11;
        int tok0 = n0 & (TT - 1);
        int gcol = d0 + c;
        int hh = gcol >> 6, dh = gcol & 63;
        size_t basei = (((size_t)(bbatch * HH + hh)) * DH + dh) * TT + tok0;
        __syncthreads();
        #pragma unroll
        for (int mi = 0; mi < 4; mi++)
            #pragma unroll
            for (int ni = 0; ni < 4; ni++) {
                int r = wm + mi * 16 + g;
                int col = wn + ni * 8 + t4 * 2;
                #pragma unroll
                for (int e = 0; e < 2; e++) {
                    f16 a = __float2half_rn(acc[mi][ni][e * 2]);
                    f16 b = __float2half_rn(acc[mi][ni][e * 2 + 1]);
                    st[(r + e * 8) * 132 + col]     = *(uint16_t*)&a;
                    st[(r + e * 8) * 132 + col + 1] = *(uint16_t*)&b;
                }
            }
        __syncthreads();
        #pragma unroll
        for (int half = 0; half < 2; half++) {
            int tb = tstart + half * 32;
            uint32_t w[16];
            #pragma unroll
            for (int j = 0; j < 16; j++) {
                uint32_t lo16 = st[(tb + 2 * j) * 132 + c];
                uint32_t hi16 = st[(tb + 2 * j + 1) * 132 + c];
                w[j] = lo16 | (hi16 << 16);
            }
            uint4* dp = (uint4*)(g_vth + basei + tb);
            dp[0] = ((uint4*)w)[0]; dp[1] = ((uint4*)w)[1];
            dp[2] = ((uint4*)w)[2]; dp[3] = ((uint4*)w)[3];
        }
    }
}

// ---------------- final output GEMM (+bias), single x single --------------------
__global__ void __launch_bounds__(256, 2) out_gemm_kernel(
        const float* __restrict__ bias, float* __restrict__ out) {
    extern __shared__ uint16_t sm[];
    int n0 = blockIdx.y * 128, d0 = blockIdx.x * 128;

    float acc[4][4][4];
    #pragma unroll
    for (int i = 0; i < 4; i++)
        #pragma unroll
        for (int j = 0; j < 4; j++)
            #pragma unroll
            for (int q = 0; q < 4; q++) acc[i][j][q] = 0.0f;

    gemm_core<0>(g_of, nullptr, g_woh, nullptr, n0, d0, sm, acc);

    int lane = threadIdx.x & 31, warp = threadIdx.x >> 5;
    int g = lane >> 2, t4 = lane & 3;
    int wm = (warp & 1) * 64, wn = (warp >> 1) * 32;

    #pragma unroll
    for (int mi = 0; mi < 4; mi++) {
        #pragma unroll
        for (int ni = 0; ni < 4; ni++) {
            int r = n0 + wm + mi * 16 + g;
            int col = d0 + wn + ni * 8 + t4 * 2;
            float b0 = bias[col], b1 = bias[col + 1];
            *(float2*)&out[(size_t)r * DD + col] =
                make_float2(acc[mi][ni][0] + b0, acc[mi][ni][1] + b1);
            *(float2*)&out[(size_t)(r + 8) * DD + col] =
                make_float2(acc[mi][ni][2] + b0, acc[mi][ni][3] + b1);
        }
    }
}

// ---------------- flash attention: interleaved QK->exp->PV, l via ones-MMA ------
// Max-free exp2 softmax (acc init -4, offset cancels in o/l). Score liveness is
// 8 fp32 (per 16-key group), so regs fit 3 CTAs/SM. l computed with a B=ones
// MMA into fp32 accumulators (d[j] = row-sum, no shuffles needed).
#define FSK 72
#define FLASH_SMEM (3*2*64*FSK*2)   /* 55296 B */
#define ONES_H2 0x3C003C00u

__global__ void __launch_bounds__(256, 3) flash_mma_kernel(
        const f16* __restrict__ Qf, const f16* __restrict__ Kb,
        const f16* __restrict__ Vth, const float* __restrict__ Gt,
        f16* __restrict__ Of) {
    extern __shared__ uint16_t smf[];
    int tid = threadIdx.x;
    int warp = tid >> 5, lane = tid & 31;
    int g = lane >> 2, t4 = lane & 3;
    int b = blockIdx.z, h = blockIdx.y;
    int q0 = blockIdx.x * 128 + warp * 16;
    size_t baseR = (size_t)b * TT * DD + h * DH;
    size_t baseV = ((size_t)b * HH + h) * DH * TT;
    uint32_t sb = smem_u32(smf);

    int lmRow = ((lane >> 4) & 1) * 8 + (lane & 7);
    int lmCol = ((lane >> 3) & 1) * 8;
    uint32_t lmOff = (uint32_t)((lmRow * FSK + lmCol) * 2);

    auto stage_load = [&](int st, int kt) {
        #pragma unroll
        for (int i = 0; i < 4; i++) {
            const int arr = i >> 1;
            int rc = tid + (i & 1) * 256;
            int row = rc >> 3, c = rc & 7;
            const f16* src = (arr == 0)
                ? Kb  + baseR + (size_t)(kt * 64 + row) * DD + c * 8
                : Vth + baseV + (size_t)row * TT + kt * 64 + c * 8;
            uint32_t dst = sb + (uint32_t)((((st * 2 + arr) * 64 + row) * FSK + c * 8) * 2);
            cpa16(dst, src);
        }
        cp_commit();
    };

    // Q fragments: direct fp16 loads (pre-scaled by proj epilogue)
    uint32_t qf[4][4];
    #pragma unroll
    for (int kc = 0; kc < 4; kc++) {
        int c = kc * 16 + t4 * 2;
        #pragma unroll
        for (int half = 0; half < 2; half++) {
            int row0 = q0 + g, row1 = q0 + 8 + g;
            int cc = c + half * 8;
            qf[kc][half * 2]     = *(const uint32_t*)&Qf[baseR + (size_t)row0 * DD + cc];
            qf[kc][half * 2 + 1] = *(const uint32_t*)&Qf[baseR + (size_t)row1 * DD + cc];
        }
    }

    float o[8][4];
    #pragma unroll
    for (int i = 0; i < 8; i++)
        #pragma unroll
        for (int j = 0; j < 4; j++) o[i][j] = 0.0f;
    float ol[4];
    #pragma unroll
    for (int j = 0; j < 4; j++) ol[j] = 0.0f;

    stage_load(0, 0);
    stage_load(1, 1);
    for (int kt = 0; kt < 32; kt++) {
        if (kt == 31) cp_wait<0>(); else cp_wait<1>();
        __syncthreads();
        if (kt < 30) stage_load((kt + 2) % 3, kt + 2);

        int st3 = kt % 3;
        uint32_t sbK = sb + (uint32_t)((st3 * 2 + 0) * 64 * FSK * 2) + lmOff;
        uint32_t sbV = sb + (uint32_t)((st3 * 2 + 1) * 64 * FSK * 2) + lmOff;

        // ---- per 16-key group: QK -> exp2 -> pack; l via ones-MMA ----
        uint32_t ap[4][4];
        #pragma unroll
        for (int kc2 = 0; kc2 < 4; kc2++) {
            float s2[8];
            #pragma unroll
            for (int j = 0; j < 8; j++) s2[j] = -4.0f;
            #pragma unroll
            for (int kc = 0; kc < 4; kc++) {
                uint32_t bm[4];
                ldsm4(bm, sbK + (uint32_t)((kc2 * 16 * FSK + kc * 16) * 2));
                mma_f16(&s2[0], qf[kc][0], qf[kc][1], qf[kc][2], qf[kc][3], bm[0], bm[1]);
                mma_f16(&s2[4], qf[kc][0], qf[kc][1], qf[kc][2], qf[kc][3], bm[2], bm[3]);
            }
            ap[kc2][0] = exp2h2(pack_h2(s2[0], s2[1]));
            ap[kc2][1] = exp2h2(pack_h2(s2[2], s2[3]));
            ap[kc2][2] = exp2h2(pack_h2(s2[4], s2[5]));
            ap[kc2][3] = exp2h2(pack_h2(s2[6], s2[7]));
            mma_f16(ol, ap[kc2][0], ap[kc2][1], ap[kc2][2], ap[kc2][3], ONES_H2, ONES_H2);
        }

        // ---- O += P V ----
        #pragma unroll
        for (int nt2 = 0; nt2 < 4; nt2++) {
            #pragma unroll
            for (int kc2 = 0; kc2 < 4; kc2++) {
                uint32_t bm[4];
                ldsm4(bm, sbV + (uint32_t)((nt2 * 16 * FSK + kc2 * 16) * 2));
                mma_f16(o[2 * nt2],     ap[kc2][0], ap[kc2][1], ap[kc2][2], ap[kc2][3], bm[0], bm[1]);
                mma_f16(o[2 * nt2 + 1], ap[kc2][0], ap[kc2][1], ap[kc2][2], ap[kc2][3], bm[2], bm[3]);
            }
        }
    }

    // l = row sums straight from the ones-MMA accumulator (no shuffles)
    float inv0 = 1.0f / ol[0], inv1 = 1.0f / ol[2];

    int row0 = q0 + g, row1 = q0 + 8 + g;
    #pragma unroll
    for (int nt = 0; nt < 8; nt++) {
        int d = nt * 8 + t4 * 2;
        size_t i0 = baseR + (size_t)row0 * DD + d;
        size_t i1 = baseR + (size_t)row1 * DD + d;
        float2 g0 = *(const float2*)&Gt[i0];
        float2 g1 = *(const float2*)&Gt[i1];
        *(uint32_t*)&Of[i0] = pack_h2(g0.x * o[nt][0] * inv0, g0.y * o[nt][1] * inv0);
        *(uint32_t*)&Of[i1] = pack_h2(g1.x * o[nt][2] * inv1, g1.y * o[nt][3] * inv1);
    }
}

// -------------------------------------------------------------------------------
extern "C" void kernel_launch(void* const* d_in, const int* in_sizes, int n_in,
                              void* d_out, int out_size) {
    const float* x   = (const float*)d_in[0];
    const int*   tok = (const int*)  d_in[1];
    const float* Wr  = (const float*)d_in[2];
    const float* Wk  = (const float*)d_in[3];
    const float* Wv  = (const float*)d_in[4];
    const float* Wo  = (const float*)d_in[5];
    const float* bo  = (const float*)d_in[6];
    const float* tmk = (const float*)d_in[7];
    const float* tmv = (const float*)d_in[8];
    const float* tmr = (const float*)d_in[9];
    float* out = (float*)d_out;

    f16 *pof, *pkb, *pvth, *pqf;
    float *pgate;
    cudaGetSymbolAddress((void**)&pof,   g_of);
    cudaGetSymbolAddress((void**)&pkb,   g_kb);
    cudaGetSymbolAddress((void**)&pvth,  g_vth);
    cudaGetSymbolAddress((void**)&pqf,   g_qf);
    cudaGetSymbolAddress((void**)&pgate, g_gate);

    cudaFuncSetAttribute(kwta_split_kernel, cudaFuncAttributeMaxDynamicSharedMemorySize, KWTA_SMEM);
    cudaFuncSetAttribute(proj_gemm_kernel,  cudaFuncAttributeMaxDynamicSharedMemorySize, GEMM_SMEM);
    cudaFuncSetAttribute(out_gemm_kernel,   cudaFuncAttributeMaxDynamicSharedMemorySize, GEMM_SMEM_S);
    cudaFuncSetAttribute(flash_mma_kernel,  cudaFuncAttributeMaxDynamicSharedMemorySize, FLASH_SMEM);

    kwta_split_kernel<<<129, 1024, KWTA_SMEM>>>(tok, Wr, Wk, Wv, Wo);
    mix_kernel<<<(NTOK * DD / 2) / 256, 256>>>(x, tmk, tmv, tmr);

    proj_gemm_kernel<<<dim3(DD / 128, NTOK / 128, 3), 256, GEMM_SMEM>>>();

    flash_mma_kernel<<<dim3(TT / 128, HH, BB), 256, FLASH_SMEM>>>(pqf, pkb, pvth, pgate, pof);

    out_gemm_kernel<<<dim3(DD / 128, NTOK / 128), 256, GEMM_SMEM_S>>>(bo, out);
}

// round 15
// speedup vs baseline: 1.5823x; 1.5823x over previous
#include <cuda_runtime.h>
#include <cuda_fp16.h>
#include <cstdint>

#define BB 2
#define TT 2048
#define DD 1024
#define HH 16
#define DH 64
#define VV 32000
#define NTOK (BB*TT)   /* 4096 */

typedef __half f16;

// ---------------- scratch (device globals; no allocations allowed) -------------
__device__ float g_gains[DD];
__device__ f16 g_xrf[NTOK*DD];                  // single fp16 (r path A)
__device__ f16 g_xkh[NTOK*DD], g_xkl[NTOK*DD];  // 2-split (k path A)
__device__ f16 g_xvf[NTOK*DD];                  // single fp16 (v path A)
__device__ f16 g_of [NTOK*DD];                  // flash out, single fp16
__device__ f16 g_wrh[DD*DD];                    // single fp16 weights (r)
__device__ f16 g_wkh[DD*DD], g_wkl[DD*DD];      // 2-split weights (k)
__device__ f16 g_wvh[DD*DD];                    // single (v)
__device__ f16 g_woh[DD*DD];                    // single (out)
__device__ f16   g_qf  [NTOK*DD];               // fp16 Q = r * QSCALE
__device__ float g_gate[NTOK*DD];               // fp32 sigmoid(r)
__device__ f16  g_kb[NTOK*DD];                  // spikes {0,1} exact
__device__ f16  g_vth[BB*HH*DH*TT];             // V^T [b][h][dh][t], single fp16

#define QSCALE (0.125f * 1.44269504f)

__device__ __forceinline__ uint32_t pack_h2(float a, float b) {
    __half2 t = __floats2half2_rn(a, b);
    return *(uint32_t*)&t;
}
__device__ __forceinline__ void split_pack_h(float a, float b, uint32_t& hi, uint32_t& lo) {
    f16 ha = __float2half_rn(a), hb = __float2half_rn(b);
    hi = ((uint32_t)*(uint16_t*)&hb << 16) | (uint32_t)*(uint16_t*)&ha;
    lo = pack_h2(a - __half2float(ha), b - __half2float(hb));
}
__device__ __forceinline__ uint32_t smem_u32(const void* p) {
    return (uint32_t)__cvta_generic_to_shared(p);
}
__device__ __forceinline__ void cpa16(uint32_t dst, const void* src) {
    asm volatile("cp.async.cg.shared.global [%0], [%1], 16;\n" :: "r"(dst), "l"(src));
}
__device__ __forceinline__ void cp_commit() { asm volatile("cp.async.commit_group;\n"); }
template <int N> __device__ __forceinline__ void cp_wait() {
    asm volatile("cp.async.wait_group %0;\n" :: "n"(N));
}
__device__ __forceinline__ void ldsm4(uint32_t r[4], uint32_t addr) {
    asm volatile("ldmatrix.sync.aligned.m8n8.x4.shared.b16 {%0,%1,%2,%3}, [%4];"
        : "=r"(r[0]), "=r"(r[1]), "=r"(r[2]), "=r"(r[3]) : "r"(addr));
}
__device__ __forceinline__ void mma_f16(float c[4], uint32_t a0, uint32_t a1,
                                        uint32_t a2, uint32_t a3,
                                        uint32_t b0, uint32_t b1) {
    asm volatile(
        "mma.sync.aligned.m16n8k16.row.col.f32.f16.f16.f32 "
        "{%0,%1,%2,%3}, {%4,%5,%6,%7}, {%8,%9}, {%0,%1,%2,%3};\n"
        : "+f"(c[0]), "+f"(c[1]), "+f"(c[2]), "+f"(c[3])
        : "r"(a0), "r"(a1), "r"(a2), "r"(a3), "r"(b0), "r"(b1));
}

// half2 exp2 via magic rounding + deg-3 poly (no MUFU). Scores here are in
// [-8, -1] (s = -4 + s_raw, |s_raw| <~ 3), far from the -16 validity edge, so
// no clamp needed.
__device__ __forceinline__ uint32_t exp2h2(uint32_t s2u) {
    __half2 s = *(__half2*)&s2u;
    const __half2 magic = __float2half2_rn(1536.0f);
    __half2 u = __hadd2(s, magic);
    __half2 f = __hsub2(s, __hsub2(u, magic));
    __half2 p = __hfma2(__hfma2(__hfma2(__float2half2_rn(0.05550411f), f,
                                        __float2half2_rn(0.24022651f)), f,
                                __float2half2_rn(0.69314718f)), f,
                        __float2half2_rn(1.0f));
    uint32_t eb = ((*(uint32_t*)&u) - 0x65F165F1u) << 10;
    __half2 r = __hmul2(p, *(__half2*)&eb);
    return *(uint32_t*)&r;
}

// ---------------- fused kWTA + weight split -------------------------------------
#define KWTA_SMEM ((VV + 1024 + 8) * 4)
__global__ void kwta_split_kernel(const int* __restrict__ tok,
                                  const float* __restrict__ Wr, const float* __restrict__ Wk,
                                  const float* __restrict__ Wv, const float* __restrict__ Wo) {
    int tid = threadIdx.x;
    if (blockIdx.x != 0) {
        int base = (blockIdx.x - 1) * blockDim.x + tid;
        for (int i = base; i < DD * DD / 2; i += 128 * blockDim.x) {
            float2 a;
            uint32_t h, l;
            a = ((const float2*)Wr)[i];
            ((uint32_t*)g_wrh)[i] = pack_h2(a.x, a.y);
            a = ((const float2*)Wk)[i];
            split_pack_h(a.x, a.y, h, l);
            ((uint32_t*)g_wkh)[i] = h; ((uint32_t*)g_wkl)[i] = l;
            a = ((const float2*)Wv)[i];
            ((uint32_t*)g_wvh)[i] = pack_h2(a.x, a.y);
            a = ((const float2*)Wo)[i];
            ((uint32_t*)g_woh)[i] = pack_h2(a.x, a.y);
        }
        return;
    }
    extern __shared__ int sh[];
    int* hist = sh;
    int* red  = sh + VV;
    int* sel  = sh + VV + 1024;
    for (int i = tid; i < VV; i += 1024) hist[i] = 0;
    __syncthreads();
    for (int i = tid; i < NTOK; i += 1024) atomicAdd(&hist[tok[i]], 1);
    __syncthreads();
    for (int p = 0; p < 5; p++) {
        int best = -1;
        for (int v = tid; v < VV; v += 1024) {
            bool skip = false;
            for (int i = 0; i < p; i++) if (sel[i] == v) skip = true;
            if (!skip) {
                int key = (hist[v] << 15) | (32767 - v);
                if (key > best) best = key;
            }
        }
        red[tid] = best;
        __syncthreads();
        for (int off = 512; off > 0; off >>= 1) {
            if (tid < off) { int o = red[tid + off]; if (o > red[tid]) red[tid] = o; }
            __syncthreads();
        }
        if (tid == 0) sel[p] = 32767 - (red[0] & 32767);
        __syncthreads();
    }
    float g = (hist[tid] > 0) ? 0.6f : 1.0f;
    for (int i = 0; i < 5; i++) if (sel[i] == tid) g = 1.5f;
    g_gains[tid] = g;
}

// ---------------- token-shift time mixing ---------------------------------------
__global__ void mix_kernel(const float* __restrict__ x,
                           const float* __restrict__ tmk,
                           const float* __restrict__ tmv,
                           const float* __restrict__ tmr) {
    int i = blockIdx.x * blockDim.x + threadIdx.x;
    if (i >= NTOK * DD / 2) return;
    int dp = i & (DD / 2 - 1);
    int t = (i >> 9) & (TT - 1);
    float2 xc = ((const float2*)x)[i];
    float2 xp = (t == 0) ? make_float2(0.f, 0.f) : ((const float2*)x)[i - DD / 2];
    int d = dp * 2;
    float g0 = g_gains[d], g1 = g_gains[d + 1];
    float2 tr = ((const float2*)tmr)[dp];
    float2 tk = ((const float2*)tmk)[dp];
    float2 tv = ((const float2*)tmv)[dp];
    float m0, m1;
    m0 = tr.x * g0; m1 = tr.y * g1;
    ((uint32_t*)g_xrf)[i] = pack_h2(m0 * xc.x + (1.f - m0) * xp.x,
                                    m1 * xc.y + (1.f - m1) * xp.y);
    uint32_t h, l;
    m0 = tk.x * g0; m1 = tk.y * g1;
    split_pack_h(m0 * xc.x + (1.f - m0) * xp.x, m1 * xc.y + (1.f - m1) * xp.y, h, l);
    ((uint32_t*)g_xkh)[i] = h; ((uint32_t*)g_xkl)[i] = l;
    m0 = tv.x * g0; m1 = tv.y * g1;
    ((uint32_t*)g_xvf)[i] = pack_h2(m0 * xc.x + (1.f - m0) * xp.x,
                                    m1 * xc.y + (1.f - m1) * xp.y);
}

// ---------------- mma GEMM core: 3-stage, single-sync, XOR-swizzled -------------
#define GEMM_SMEM   (3*4*128*64)   /* 98304 B (k mode) */
#define GEMM_SMEM_S (3*2*128*64)   /* 49152 B (single mode) */

template <int KM>
__device__ __forceinline__ void gemm_core(
        const f16* __restrict__ A0, const f16* __restrict__ A1,
        const f16* __restrict__ W0, const f16* __restrict__ W1,
        int n0, int d0, uint16_t* sm, float acc[4][4][4]) {
    const int NARR = KM ? 4 : 2;
    int t = threadIdx.x;
    int lane = t & 31, warp = t >> 5;
    int wm = (warp & 1) * 64, wn = (warp >> 1) * 32;
    uint32_t sb = smem_u32(sm);

    int aRowOff = (lane & 7) + ((lane & 8) ? 8 : 0);
    int aChunk  = lane >> 4;
    int wRowOff = (lane & 7) + ((lane >> 4) & 1) * 8;
    int wChunk  = (lane >> 3) & 1;

    const f16* baseP[4];
    if (KM) {
        baseP[0] = A0 + (size_t)n0 * DD; baseP[1] = A1 + (size_t)n0 * DD;
        baseP[2] = W0 + (size_t)d0 * DD; baseP[3] = W1 + (size_t)d0 * DD;
    } else {
        baseP[0] = A0 + (size_t)n0 * DD; baseP[1] = W0 + (size_t)d0 * DD;
        baseP[2] = nullptr; baseP[3] = nullptr;
    }

    auto stage_load = [&](int st, int k0) {
        #pragma unroll
        for (int i = 0; i < 2 * NARR; i++) {
            const int arr = i >> 1;
            int rc = t + (i & 1) * 256;
            int row = rc >> 2, c = rc & 3;
            const f16* src = baseP[arr] + (size_t)row * DD + k0 + c * 8;
            int phys = c ^ ((row >> 1) & 3);
            uint32_t dst = sb + (uint32_t)(st * NARR * 8192 + arr * 8192 + row * 64 + phys * 16);
            cpa16(dst, src);
        }
        cp_commit();
    };

    stage_load(0, 0);
    stage_load(1, 32);
    for (int it = 0; it < 32; it++) {
        if (it == 31) cp_wait<0>(); else cp_wait<1>();
        __syncthreads();
        if (it < 30) stage_load((it + 2) % 3, (it + 2) * 32);

        int st = it % 3;
        uint32_t base = sb + (uint32_t)(st * NARR * 8192);
        uint32_t bA0 = base;
        uint32_t bA1 = base + 8192;
        uint32_t bW0 = base + (KM ? 16384 : 8192);
        uint32_t bW1 = base + 24576;

        #pragma unroll
        for (int ks = 0; ks < 2; ks++) {
            int kc8 = ks * 2;
            uint32_t ah[4][4], al[4][4];
            #pragma unroll
            for (int mi = 0; mi < 4; mi++) {
                int row = wm + mi * 16 + aRowOff;
                int ph = (kc8 + aChunk) ^ ((row >> 1) & 3);
                uint32_t off = (uint32_t)(row * 64 + ph * 16);
                ldsm4(ah[mi], bA0 + off);
                if (KM) ldsm4(al[mi], bA1 + off);
            }
            uint32_t bh[4][2], bl[4][2];
            #pragma unroll
            for (int pair = 0; pair < 2; pair++) {
                int row = wn + pair * 16 + wRowOff;
                int ph = (kc8 + wChunk) ^ ((row >> 1) & 3);
                uint32_t off = (uint32_t)(row * 64 + ph * 16);
                uint32_t qh[4];
                ldsm4(qh, bW0 + off);
                bh[pair * 2][0] = qh[0]; bh[pair * 2][1] = qh[1];
                bh[pair * 2 + 1][0] = qh[2]; bh[pair * 2 + 1][1] = qh[3];
                if (KM) {
                    uint32_t ql[4];
                    ldsm4(ql, bW1 + off);
                    bl[pair * 2][0] = ql[0]; bl[pair * 2][1] = ql[1];
                    bl[pair * 2 + 1][0] = ql[2]; bl[pair * 2 + 1][1] = ql[3];
                }
            }
            #pragma unroll
            for (int ni = 0; ni < 4; ni++)
                #pragma unroll
                for (int mi = 0; mi < 4; mi++) {
                    mma_f16(acc[mi][ni], ah[mi][0], ah[mi][1], ah[mi][2], ah[mi][3],
                            bh[ni][0], bh[ni][1]);
                    if (KM) {
                        mma_f16(acc[mi][ni], ah[mi][0], ah[mi][1], ah[mi][2], ah[mi][3],
                                bl[ni][0], bl[ni][1]);
                        mma_f16(acc[mi][ni], al[mi][0], al[mi][1], al[mi][2], al[mi][3],
                                bh[ni][0], bh[ni][1]);
                    }
                }
        }
    }
}

// ---------------- fused projection GEMMs (z: 0=k spike, 1=r, 2=v transposed) ----
__global__ void __launch_bounds__(256, 2) proj_gemm_kernel() {
    extern __shared__ uint16_t sm[];
    int mode = blockIdx.z;
    int n0 = blockIdx.y * 128, d0 = blockIdx.x * 128;

    float acc[4][4][4];
    #pragma unroll
    for (int i = 0; i < 4; i++)
        #pragma unroll
        for (int j = 0; j < 4; j++)
            #pragma unroll
            for (int q = 0; q < 4; q++) acc[i][j][q] = 0.0f;

    if (mode == 0)      gemm_core<1>(g_xkh, g_xkl, g_wkh, g_wkl, n0, d0, sm, acc);
    else if (mode == 1) gemm_core<0>(g_xrf, nullptr, g_wrh, nullptr, n0, d0, sm, acc);
    else                gemm_core<0>(g_xvf, nullptr, g_wvh, nullptr, n0, d0, sm, acc);

    int tid = threadIdx.x;
    int lane = tid & 31, warp = tid >> 5;
    int g = lane >> 2, t4 = lane & 3;
    int wm = (warp & 1) * 64, wn = (warp >> 1) * 32;

    if (mode == 1) {
        #pragma unroll
        for (int mi = 0; mi < 4; mi++)
            #pragma unroll
            for (int ni = 0; ni < 4; ni++) {
                int r = n0 + wm + mi * 16 + g;
                int col = d0 + wn + ni * 8 + t4 * 2;
                float v0 = acc[mi][ni][0], v1 = acc[mi][ni][1];
                float v2 = acc[mi][ni][2], v3 = acc[mi][ni][3];
                *(uint32_t*)&g_qf[(size_t)r * DD + col]       = pack_h2(v0 * QSCALE, v1 * QSCALE);
                *(uint32_t*)&g_qf[(size_t)(r + 8) * DD + col] = pack_h2(v2 * QSCALE, v3 * QSCALE);
                *(float2*)&g_gate[(size_t)r * DD + col] =
                    make_float2(1.f / (1.f + __expf(-v0)), 1.f / (1.f + __expf(-v1)));
                *(float2*)&g_gate[(size_t)(r + 8) * DD + col] =
                    make_float2(1.f / (1.f + __expf(-v2)), 1.f / (1.f + __expf(-v3)));
            }
    } else if (mode == 0) {
        #pragma unroll
        for (int mi = 0; mi < 4; mi++)
            #pragma unroll
            for (int ni = 0; ni < 4; ni++) {
                int r = n0 + wm + mi * 16 + g;
                int col = d0 + wn + ni * 8 + t4 * 2;
                *(uint32_t*)&g_kb[(size_t)r * DD + col] =
                    pack_h2(acc[mi][ni][0] > 0.5f ? 1.0f : 0.0f,
                            acc[mi][ni][1] > 0.5f ? 1.0f : 0.0f);
                *(uint32_t*)&g_kb[(size_t)(r + 8) * DD + col] =
                    pack_h2(acc[mi][ni][2] > 0.5f ? 1.0f : 0.0f,
                            acc[mi][ni][3] > 0.5f ? 1.0f : 0.0f);
            }
    } else {
        // V: smem transpose -> coalesced [b][h][dh][t] single-fp16 stores
        uint16_t* st = sm;
        int c = tid >> 1;
        int tstart = (tid & 1) * 64;
        int bbatch = n0 >> 11;
        int tok0 = n0 & (TT - 1);
        int gcol = d0 + c;
        int hh = gcol >> 6, dh = gcol & 63;
        size_t basei = (((size_t)(bbatch * HH + hh)) * DH + dh) * TT + tok0;
        __syncthreads();
        #pragma unroll
        for (int mi = 0; mi < 4; mi++)
            #pragma unroll
            for (int ni = 0; ni < 4; ni++) {
                int r = wm + mi * 16 + g;
                int col = wn + ni * 8 + t4 * 2;
                #pragma unroll
                for (int e = 0; e < 2; e++) {
                    f16 a = __float2half_rn(acc[mi][ni][e * 2]);
                    f16 b = __float2half_rn(acc[mi][ni][e * 2 + 1]);
                    st[(r + e * 8) * 132 + col]     = *(uint16_t*)&a;
                    st[(r + e * 8) * 132 + col + 1] = *(uint16_t*)&b;
                }
            }
        __syncthreads();
        #pragma unroll
        for (int half = 0; half < 2; half++) {
            int tb = tstart + half * 32;
            uint32_t w[16];
            #pragma unroll
            for (int j = 0; j < 16; j++) {
                uint32_t lo16 = st[(tb + 2 * j) * 132 + c];
                uint32_t hi16 = st[(tb + 2 * j + 1) * 132 + c];
                w[j] = lo16 | (hi16 << 16);
            }
            uint4* dp = (uint4*)(g_vth + basei + tb);
            dp[0] = ((uint4*)w)[0]; dp[1] = ((uint4*)w)[1];
            dp[2] = ((uint4*)w)[2]; dp[3] = ((uint4*)w)[3];
        }
    }
}

// ---------------- final output GEMM (+bias), single x single --------------------
__global__ void __launch_bounds__(256, 2) out_gemm_kernel(
        const float* __restrict__ bias, float* __restrict__ out) {
    extern __shared__ uint16_t sm[];
    int n0 = blockIdx.y * 128, d0 = blockIdx.x * 128;

    float acc[4][4][4];
    #pragma unroll
    for (int i = 0; i < 4; i++)
        #pragma unroll
        for (int j = 0; j < 4; j++)
            #pragma unroll
            for (int q = 0; q < 4; q++) acc[i][j][q] = 0.0f;

    gemm_core<0>(g_of, nullptr, g_woh, nullptr, n0, d0, sm, acc);

    int lane = threadIdx.x & 31, warp = threadIdx.x >> 5;
    int g = lane >> 2, t4 = lane & 3;
    int wm = (warp & 1) * 64, wn = (warp >> 1) * 32;

    #pragma unroll
    for (int mi = 0; mi < 4; mi++) {
        #pragma unroll
        for (int ni = 0; ni < 4; ni++) {
            int r = n0 + wm + mi * 16 + g;
            int col = d0 + wn + ni * 8 + t4 * 2;
            float b0 = bias[col], b1 = bias[col + 1];
            *(float2*)&out[(size_t)r * DD + col] =
                make_float2(acc[mi][ni][0] + b0, acc[mi][ni][1] + b1);
            *(float2*)&out[(size_t)(r + 8) * DD + col] =
                make_float2(acc[mi][ni][2] + b0, acc[mi][ni][3] + b1);
        }
    }
}

// ---------------- flash attention: batched QK / exp2 / PV phases (R11) ----------
// Max-free exp2 softmax (acc init -4; uniform offset cancels in o/l).
// l via one ones-MMA per kc2, issued inside the PV batch (nt2==0) so the 4
// ol-chained MMAs are spaced ~8 independent MMAs apart.
#define FSK 72
#define FLASH_SMEM (3*2*64*FSK*2)   /* 55296 B */
#define ONES_H2 0x3C003C00u

__global__ void __launch_bounds__(256) flash_mma_kernel(
        const f16* __restrict__ Qf, const f16* __restrict__ Kb,
        const f16* __restrict__ Vth, const float* __restrict__ Gt,
        f16* __restrict__ Of) {
    extern __shared__ uint16_t smf[];
    int tid = threadIdx.x;
    int warp = tid >> 5, lane = tid & 31;
    int g = lane >> 2, t4 = lane & 3;
    int b = blockIdx.z, h = blockIdx.y;
    int q0 = blockIdx.x * 128 + warp * 16;
    size_t baseR = (size_t)b * TT * DD + h * DH;
    size_t baseV = ((size_t)b * HH + h) * DH * TT;
    uint32_t sb = smem_u32(smf);

    int lmRow = ((lane >> 4) & 1) * 8 + (lane & 7);
    int lmCol = ((lane >> 3) & 1) * 8;

    auto stage_load = [&](int st, int kt) {
        #pragma unroll
        for (int i = 0; i < 4; i++) {
            const int arr = i >> 1;
            int rc = tid + (i & 1) * 256;
            int row = rc >> 3, c = rc & 7;
            const f16* src = (arr == 0)
                ? Kb  + baseR + (size_t)(kt * 64 + row) * DD + c * 8
                : Vth + baseV + (size_t)row * TT + kt * 64 + c * 8;
            uint32_t dst = sb + (uint32_t)((((st * 2 + arr) * 64 + row) * FSK + c * 8) * 2);
            cpa16(dst, src);
        }
        cp_commit();
    };

    // Q fragments: direct fp16 loads (pre-scaled by proj epilogue)
    uint32_t qf[4][4];
    #pragma unroll
    for (int kc = 0; kc < 4; kc++) {
        int c = kc * 16 + t4 * 2;
        #pragma unroll
        for (int half = 0; half < 2; half++) {
            int row0 = q0 + g, row1 = q0 + 8 + g;
            int cc = c + half * 8;
            qf[kc][half * 2]     = *(const uint32_t*)&Qf[baseR + (size_t)row0 * DD + cc];
            qf[kc][half * 2 + 1] = *(const uint32_t*)&Qf[baseR + (size_t)row1 * DD + cc];
        }
    }

    float o[8][4];
    #pragma unroll
    for (int i = 0; i < 8; i++)
        #pragma unroll
        for (int j = 0; j < 4; j++) o[i][j] = 0.0f;
    float ol[4];
    #pragma unroll
    for (int j = 0; j < 4; j++) ol[j] = 0.0f;

    stage_load(0, 0);
    stage_load(1, 1);
    for (int kt = 0; kt < 32; kt++) {
        if (kt == 31) cp_wait<0>(); else cp_wait<1>();
        __syncthreads();
        if (kt < 30) stage_load((kt + 2) % 3, kt + 2);

        int st3 = kt % 3;
        uint32_t sbK = sb + (uint32_t)((st3 * 2 + 0) * 64 * FSK * 2);
        uint32_t sbV = sb + (uint32_t)((st3 * 2 + 1) * 64 * FSK * 2);

        // ---- phase 1: S = Q K^T across all 8 score tiles (init -4) ----
        float s[8][4];
        #pragma unroll
        for (int i = 0; i < 8; i++)
            #pragma unroll
            for (int j = 0; j < 4; j++) s[i][j] = -4.0f;
        #pragma unroll
        for (int nt2 = 0; nt2 < 4; nt2++) {
            #pragma unroll
            for (int kc = 0; kc < 4; kc++) {
                uint32_t bm[4];
                uint32_t addr = sbK + (uint32_t)(((nt2 * 16 + lmRow) * FSK + kc * 16 + lmCol) * 2);
                ldsm4(bm, addr);
                mma_f16(s[2 * nt2],     qf[kc][0], qf[kc][1], qf[kc][2], qf[kc][3], bm[0], bm[1]);
                mma_f16(s[2 * nt2 + 1], qf[kc][0], qf[kc][1], qf[kc][2], qf[kc][3], bm[2], bm[3]);
            }
        }

        // ---- phase 2: P = exp2(S) in half2 (fma/alu pipes, batched) ----
        uint32_t ap[4][4];
        #pragma unroll
        for (int kc2 = 0; kc2 < 4; kc2++) {
            int ta = 2 * kc2, tb = 2 * kc2 + 1;
            ap[kc2][0] = exp2h2(pack_h2(s[ta][0], s[ta][1]));
            ap[kc2][1] = exp2h2(pack_h2(s[ta][2], s[ta][3]));
            ap[kc2][2] = exp2h2(pack_h2(s[tb][0], s[tb][1]));
            ap[kc2][3] = exp2h2(pack_h2(s[tb][2], s[tb][3]));
        }

        // ---- phase 3: O += P V, with l ones-MMAs riding the batch ----
        #pragma unroll
        for (int nt2 = 0; nt2 < 4; nt2++) {
            #pragma unroll
            for (int kc2 = 0; kc2 < 4; kc2++) {
                uint32_t bm[4];
                uint32_t addr = sbV + (uint32_t)(((nt2 * 16 + lmRow) * FSK + kc2 * 16 + lmCol) * 2);
                ldsm4(bm, addr);
                mma_f16(o[2 * nt2],     ap[kc2][0], ap[kc2][1], ap[kc2][2], ap[kc2][3], bm[0], bm[1]);
                mma_f16(o[2 * nt2 + 1], ap[kc2][0], ap[kc2][1], ap[kc2][2], ap[kc2][3], bm[2], bm[3]);
                if (nt2 == 0)
                    mma_f16(ol, ap[kc2][0], ap[kc2][1], ap[kc2][2], ap[kc2][3], ONES_H2, ONES_H2);
            }
        }
    }

    // l = row sums straight from the ones-MMA accumulator (no shuffles)
    float inv0 = 1.0f / ol[0], inv1 = 1.0f / ol[2];

    int row0 = q0 + g, row1 = q0 + 8 + g;
    #pragma unroll
    for (int nt = 0; nt < 8; nt++) {
        int d = nt * 8 + t4 * 2;
        size_t i0 = baseR + (size_t)row0 * DD + d;
        size_t i1 = baseR + (size_t)row1 * DD + d;
        float2 g0 = *(const float2*)&Gt[i0];
        float2 g1 = *(const float2*)&Gt[i1];
        *(uint32_t*)&Of[i0] = pack_h2(g0.x * o[nt][0] * inv0, g0.y * o[nt][1] * inv0);
        *(uint32_t*)&Of[i1] = pack_h2(g1.x * o[nt][2] * inv1, g1.y * o[nt][3] * inv1);
    }
}

// -------------------------------------------------------------------------------
extern "C" void kernel_launch(void* const* d_in, const int* in_sizes, int n_in,
                              void* d_out, int out_size) {
    const float* x   = (const float*)d_in[0];
    const int*   tok = (const int*)  d_in[1];
    const float* Wr  = (const float*)d_in[2];
    const float* Wk  = (const float*)d_in[3];
    const float* Wv  = (const float*)d_in[4];
    const float* Wo  = (const float*)d_in[5];
    const float* bo  = (const float*)d_in[6];
    const float* tmk = (const float*)d_in[7];
    const float* tmv = (const float*)d_in[8];
    const float* tmr = (const float*)d_in[9];
    float* out = (float*)d_out;

    f16 *pof, *pkb, *pvth, *pqf;
    float *pgate;
    cudaGetSymbolAddress((void**)&pof,   g_of);
    cudaGetSymbolAddress((void**)&pkb,   g_kb);
    cudaGetSymbolAddress((void**)&pvth,  g_vth);
    cudaGetSymbolAddress((void**)&pqf,   g_qf);
    cudaGetSymbolAddress((void**)&pgate, g_gate);

    cudaFuncSetAttribute(kwta_split_kernel, cudaFuncAttributeMaxDynamicSharedMemorySize, KWTA_SMEM);
    cudaFuncSetAttribute(proj_gemm_kernel,  cudaFuncAttributeMaxDynamicSharedMemorySize, GEMM_SMEM);
    cudaFuncSetAttribute(out_gemm_kernel,   cudaFuncAttributeMaxDynamicSharedMemorySize, GEMM_SMEM_S);
    cudaFuncSetAttribute(flash_mma_kernel,  cudaFuncAttributeMaxDynamicSharedMemorySize, FLASH_SMEM);

    kwta_split_kernel<<<129, 1024, KWTA_SMEM>>>(tok, Wr, Wk, Wv, Wo);
    mix_kernel<<<(NTOK * DD / 2) / 256, 256>>>(x, tmk, tmv, tmr);

    proj_gemm_kernel<<<dim3(DD / 128, NTOK / 128, 3), 256, GEMM_SMEM>>>();

    flash_mma_kernel<<<dim3(TT / 128, HH, BB), 256, FLASH_SMEM>>>(pqf, pkb, pvth, pgate, pof);

    out_gemm_kernel<<<dim3(DD / 128, NTOK / 128), 256, GEMM_SMEM_S>>>(bo, out);
}

// round 16
// speedup vs baseline: 1.6030x; 1.0131x over previous
#include <cuda_runtime.h>
#include <cuda_fp16.h>
#include <cstdint>

#define BB 2
#define TT 2048
#define DD 1024
#define HH 16
#define DH 64
#define VV 32000
#define NTOK (BB*TT)   /* 4096 */

typedef __half f16;

// ---------------- scratch (device globals; no allocations allowed) -------------
__device__ float g_gains[DD];
__device__ f16 g_xrf[NTOK*DD];                  // single fp16 (r path A)
__device__ f16 g_xkh[NTOK*DD], g_xkl[NTOK*DD];  // 2-split (k path A)
__device__ f16 g_xvf[NTOK*DD];                  // single fp16 (v path A)
__device__ f16 g_of [NTOK*DD];                  // flash out, single fp16
__device__ f16 g_wrh[DD*DD];                    // single fp16 weights (r)
__device__ f16 g_wkh[DD*DD], g_wkl[DD*DD];      // 2-split weights (k)
__device__ f16 g_wvh[DD*DD];                    // single (v)
__device__ f16 g_woh[DD*DD];                    // single (out)
__device__ f16   g_qf  [NTOK*DD];               // fp16 Q = r * QSCALE
__device__ float g_gate[NTOK*DD];               // fp32 sigmoid(r)
__device__ f16  g_kb[NTOK*DD];                  // spikes {0,1} exact
__device__ f16  g_vth[BB*HH*DH*TT];             // V^T [b][h][dh][t], single fp16

#define QSCALE (0.125f * 1.44269504f)

__device__ __forceinline__ uint32_t pack_h2(float a, float b) {
    __half2 t = __floats2half2_rn(a, b);
    return *(uint32_t*)&t;
}
__device__ __forceinline__ void split_pack_h(float a, float b, uint32_t& hi, uint32_t& lo) {
    f16 ha = __float2half_rn(a), hb = __float2half_rn(b);
    hi = ((uint32_t)*(uint16_t*)&hb << 16) | (uint32_t)*(uint16_t*)&ha;
    lo = pack_h2(a - __half2float(ha), b - __half2float(hb));
}
__device__ __forceinline__ uint32_t smem_u32(const void* p) {
    return (uint32_t)__cvta_generic_to_shared(p);
}
__device__ __forceinline__ void cpa16(uint32_t dst, const void* src) {
    asm volatile("cp.async.cg.shared.global [%0], [%1], 16;\n" :: "r"(dst), "l"(src));
}
__device__ __forceinline__ void cp_commit() { asm volatile("cp.async.commit_group;\n"); }
template <int N> __device__ __forceinline__ void cp_wait() {
    asm volatile("cp.async.wait_group %0;\n" :: "n"(N));
}
__device__ __forceinline__ void ldsm4(uint32_t r[4], uint32_t addr) {
    asm volatile("ldmatrix.sync.aligned.m8n8.x4.shared.b16 {%0,%1,%2,%3}, [%4];"
        : "=r"(r[0]), "=r"(r[1]), "=r"(r[2]), "=r"(r[3]) : "r"(addr));
}
__device__ __forceinline__ void mma_f16(float c[4], uint32_t a0, uint32_t a1,
                                        uint32_t a2, uint32_t a3,
                                        uint32_t b0, uint32_t b1) {
    asm volatile(
        "mma.sync.aligned.m16n8k16.row.col.f32.f16.f16.f32 "
        "{%0,%1,%2,%3}, {%4,%5,%6,%7}, {%8,%9}, {%0,%1,%2,%3};\n"
        : "+f"(c[0]), "+f"(c[1]), "+f"(c[2]), "+f"(c[3])
        : "r"(a0), "r"(a1), "r"(a2), "r"(a3), "r"(b0), "r"(b1));
}
// fp16-accumulator MMA: D packed half2 {row g | row g+8}, layout == A-fragment
__device__ __forceinline__ void mma_f16_h2(uint32_t c[2], uint32_t a0, uint32_t a1,
                                           uint32_t a2, uint32_t a3,
                                           uint32_t b0, uint32_t b1) {
    asm volatile(
        "mma.sync.aligned.m16n8k16.row.col.f16.f16.f16.f16 "
        "{%0,%1}, {%2,%3,%4,%5}, {%6,%7}, {%0,%1};\n"
        : "+r"(c[0]), "+r"(c[1])
        : "r"(a0), "r"(a1), "r"(a2), "r"(a3), "r"(b0), "r"(b1));
}

// half2 exp2 via magic rounding + deg-3 poly (no MUFU). Scores here are in
// [-8, -1] (s = -4 + s_raw, |s_raw| <~ 3), far from the -16 validity edge.
__device__ __forceinline__ uint32_t exp2h2(uint32_t s2u) {
    __half2 s = *(__half2*)&s2u;
    const __half2 magic = __float2half2_rn(1536.0f);
    __half2 u = __hadd2(s, magic);
    __half2 f = __hsub2(s, __hsub2(u, magic));
    __half2 p = __hfma2(__hfma2(__hfma2(__float2half2_rn(0.05550411f), f,
                                        __float2half2_rn(0.24022651f)), f,
                                __float2half2_rn(0.69314718f)), f,
                        __float2half2_rn(1.0f));
    uint32_t eb = ((*(uint32_t*)&u) - 0x65F165F1u) << 10;
    __half2 r = __hmul2(p, *(__half2*)&eb);
    return *(uint32_t*)&r;
}

// ---------------- fused kWTA + weight split -------------------------------------
#define KWTA_SMEM ((VV + 1024 + 8) * 4)
__global__ void kwta_split_kernel(const int* __restrict__ tok,
                                  const float* __restrict__ Wr, const float* __restrict__ Wk,
                                  const float* __restrict__ Wv, const float* __restrict__ Wo) {
    int tid = threadIdx.x;
    if (blockIdx.x != 0) {
        int base = (blockIdx.x - 1) * blockDim.x + tid;
        for (int i = base; i < DD * DD / 2; i += 128 * blockDim.x) {
            float2 a;
            uint32_t h, l;
            a = ((const float2*)Wr)[i];
            ((uint32_t*)g_wrh)[i] = pack_h2(a.x, a.y);
            a = ((const float2*)Wk)[i];
            split_pack_h(a.x, a.y, h, l);
            ((uint32_t*)g_wkh)[i] = h; ((uint32_t*)g_wkl)[i] = l;
            a = ((const float2*)Wv)[i];
            ((uint32_t*)g_wvh)[i] = pack_h2(a.x, a.y);
            a = ((const float2*)Wo)[i];
            ((uint32_t*)g_woh)[i] = pack_h2(a.x, a.y);
        }
        return;
    }
    extern __shared__ int sh[];
    int* hist = sh;
    int* red  = sh + VV;
    int* sel  = sh + VV + 1024;
    for (int i = tid; i < VV; i += 1024) hist[i] = 0;
    __syncthreads();
    for (int i = tid; i < NTOK; i += 1024) atomicAdd(&hist[tok[i]], 1);
    __syncthreads();
    for (int p = 0; p < 5; p++) {
        int best = -1;
        for (int v = tid; v < VV; v += 1024) {
            bool skip = false;
            for (int i = 0; i < p; i++) if (sel[i] == v) skip = true;
            if (!skip) {
                int key = (hist[v] << 15) | (32767 - v);
                if (key > best) best = key;
            }
        }
        red[tid] = best;
        __syncthreads();
        for (int off = 512; off > 0; off >>= 1) {
            if (tid < off) { int o = red[tid + off]; if (o > red[tid]) red[tid] = o; }
            __syncthreads();
        }
        if (tid == 0) sel[p] = 32767 - (red[0] & 32767);
        __syncthreads();
    }
    float g = (hist[tid] > 0) ? 0.6f : 1.0f;
    for (int i = 0; i < 5; i++) if (sel[i] == tid) g = 1.5f;
    g_gains[tid] = g;
}

// ---------------- token-shift time mixing ---------------------------------------
__global__ void mix_kernel(const float* __restrict__ x,
                           const float* __restrict__ tmk,
                           const float* __restrict__ tmv,
                           const float* __restrict__ tmr) {
    int i = blockIdx.x * blockDim.x + threadIdx.x;
    if (i >= NTOK * DD / 2) return;
    int dp = i & (DD / 2 - 1);
    int t = (i >> 9) & (TT - 1);
    float2 xc = ((const float2*)x)[i];
    float2 xp = (t == 0) ? make_float2(0.f, 0.f) : ((const float2*)x)[i - DD / 2];
    int d = dp * 2;
    float g0 = g_gains[d], g1 = g_gains[d + 1];
    float2 tr = ((const float2*)tmr)[dp];
    float2 tk = ((const float2*)tmk)[dp];
    float2 tv = ((const float2*)tmv)[dp];
    float m0, m1;
    m0 = tr.x * g0; m1 = tr.y * g1;
    ((uint32_t*)g_xrf)[i] = pack_h2(m0 * xc.x + (1.f - m0) * xp.x,
                                    m1 * xc.y + (1.f - m1) * xp.y);
    uint32_t h, l;
    m0 = tk.x * g0; m1 = tk.y * g1;
    split_pack_h(m0 * xc.x + (1.f - m0) * xp.x, m1 * xc.y + (1.f - m1) * xp.y, h, l);
    ((uint32_t*)g_xkh)[i] = h; ((uint32_t*)g_xkl)[i] = l;
    m0 = tv.x * g0; m1 = tv.y * g1;
    ((uint32_t*)g_xvf)[i] = pack_h2(m0 * xc.x + (1.f - m0) * xp.x,
                                    m1 * xc.y + (1.f - m1) * xp.y);
}

// ---------------- mma GEMM core: 3-stage, single-sync, XOR-swizzled -------------
#define GEMM_SMEM   (3*4*128*64)   /* 98304 B (k mode) */
#define GEMM_SMEM_S (3*2*128*64)   /* 49152 B (single mode) */

template <int KM>
__device__ __forceinline__ void gemm_core(
        const f16* __restrict__ A0, const f16* __restrict__ A1,
        const f16* __restrict__ W0, const f16* __restrict__ W1,
        int n0, int d0, uint16_t* sm, float acc[4][4][4]) {
    const int NARR = KM ? 4 : 2;
    int t = threadIdx.x;
    int lane = t & 31, warp = t >> 5;
    int wm = (warp & 1) * 64, wn = (warp >> 1) * 32;
    uint32_t sb = smem_u32(sm);

    int aRowOff = (lane & 7) + ((lane & 8) ? 8 : 0);
    int aChunk  = lane >> 4;
    int wRowOff = (lane & 7) + ((lane >> 4) & 1) * 8;
    int wChunk  = (lane >> 3) & 1;

    const f16* baseP[4];
    if (KM) {
        baseP[0] = A0 + (size_t)n0 * DD; baseP[1] = A1 + (size_t)n0 * DD;
        baseP[2] = W0 + (size_t)d0 * DD; baseP[3] = W1 + (size_t)d0 * DD;
    } else {
        baseP[0] = A0 + (size_t)n0 * DD; baseP[1] = W0 + (size_t)d0 * DD;
        baseP[2] = nullptr; baseP[3] = nullptr;
    }

    auto stage_load = [&](int st, int k0) {
        #pragma unroll
        for (int i = 0; i < 2 * NARR; i++) {
            const int arr = i >> 1;
            int rc = t + (i & 1) * 256;
            int row = rc >> 2, c = rc & 3;
            const f16* src = baseP[arr] + (size_t)row * DD + k0 + c * 8;
            int phys = c ^ ((row >> 1) & 3);
            uint32_t dst = sb + (uint32_t)(st * NARR * 8192 + arr * 8192 + row * 64 + phys * 16);
            cpa16(dst, src);
        }
        cp_commit();
    };

    stage_load(0, 0);
    stage_load(1, 32);
    for (int it = 0; it < 32; it++) {
        if (it == 31) cp_wait<0>(); else cp_wait<1>();
        __syncthreads();
        if (it < 30) stage_load((it + 2) % 3, (it + 2) * 32);

        int st = it % 3;
        uint32_t base = sb + (uint32_t)(st * NARR * 8192);
        uint32_t bA0 = base;
        uint32_t bA1 = base + 8192;
        uint32_t bW0 = base + (KM ? 16384 : 8192);
        uint32_t bW1 = base + 24576;

        #pragma unroll
        for (int ks = 0; ks < 2; ks++) {
            int kc8 = ks * 2;
            uint32_t ah[4][4], al[4][4];
            #pragma unroll
            for (int mi = 0; mi < 4; mi++) {
                int row = wm + mi * 16 + aRowOff;
                int ph = (kc8 + aChunk) ^ ((row >> 1) & 3);
                uint32_t off = (uint32_t)(row * 64 + ph * 16);
                ldsm4(ah[mi], bA0 + off);
                if (KM) ldsm4(al[mi], bA1 + off);
            }
            uint32_t bh[4][2], bl[4][2];
            #pragma unroll
            for (int pair = 0; pair < 2; pair++) {
                int row = wn + pair * 16 + wRowOff;
                int ph = (kc8 + wChunk) ^ ((row >> 1) & 3);
                uint32_t off = (uint32_t)(row * 64 + ph * 16);
                uint32_t qh[4];
                ldsm4(qh, bW0 + off);
                bh[pair * 2][0] = qh[0]; bh[pair * 2][1] = qh[1];
                bh[pair * 2 + 1][0] = qh[2]; bh[pair * 2 + 1][1] = qh[3];
                if (KM) {
                    uint32_t ql[4];
                    ldsm4(ql, bW1 + off);
                    bl[pair * 2][0] = ql[0]; bl[pair * 2][1] = ql[1];
                    bl[pair * 2 + 1][0] = ql[2]; bl[pair * 2 + 1][1] = ql[3];
                }
            }
            #pragma unroll
            for (int ni = 0; ni < 4; ni++)
                #pragma unroll
                for (int mi = 0; mi < 4; mi++) {
                    mma_f16(acc[mi][ni], ah[mi][0], ah[mi][1], ah[mi][2], ah[mi][3],
                            bh[ni][0], bh[ni][1]);
                    if (KM) {
                        mma_f16(acc[mi][ni], ah[mi][0], ah[mi][1], ah[mi][2], ah[mi][3],
                                bl[ni][0], bl[ni][1]);
                        mma_f16(acc[mi][ni], al[mi][0], al[mi][1], al[mi][2], al[mi][3],
                                bh[ni][0], bh[ni][1]);
                    }
                }
        }
    }
}

// ---------------- fused projection GEMMs (z: 0=k spike, 1=r, 2=v transposed) ----
__global__ void __launch_bounds__(256, 2) proj_gemm_kernel() {
    extern __shared__ uint16_t sm[];
    int mode = blockIdx.z;
    int n0 = blockIdx.y * 128, d0 = blockIdx.x * 128;

    float acc[4][4][4];
    #pragma unroll
    for (int i = 0; i < 4; i++)
        #pragma unroll
        for (int j = 0; j < 4; j++)
            #pragma unroll
            for (int q = 0; q < 4; q++) acc[i][j][q] = 0.0f;

    if (mode == 0)      gemm_core<1>(g_xkh, g_xkl, g_wkh, g_wkl, n0, d0, sm, acc);
    else if (mode == 1) gemm_core<0>(g_xrf, nullptr, g_wrh, nullptr, n0, d0, sm, acc);
    else                gemm_core<0>(g_xvf, nullptr, g_wvh, nullptr, n0, d0, sm, acc);

    int tid = threadIdx.x;
    int lane = tid & 31, warp = tid >> 5;
    int g = lane >> 2, t4 = lane & 3;
    int wm = (warp & 1) * 64, wn = (warp >> 1) * 32;

    if (mode == 1) {
        #pragma unroll
        for (int mi = 0; mi < 4; mi++)
            #pragma unroll
            for (int ni = 0; ni < 4; ni++) {
                int r = n0 + wm + mi * 16 + g;
                int col = d0 + wn + ni * 8 + t4 * 2;
                float v0 = acc[mi][ni][0], v1 = acc[mi][ni][1];
                float v2 = acc[mi][ni][2], v3 = acc[mi][ni][3];
                *(uint32_t*)&g_qf[(size_t)r * DD + col]       = pack_h2(v0 * QSCALE, v1 * QSCALE);
                *(uint32_t*)&g_qf[(size_t)(r + 8) * DD + col] = pack_h2(v2 * QSCALE, v3 * QSCALE);
                *(float2*)&g_gate[(size_t)r * DD + col] =
                    make_float2(1.f / (1.f + __expf(-v0)), 1.f / (1.f + __expf(-v1)));
                *(float2*)&g_gate[(size_t)(r + 8) * DD + col] =
                    make_float2(1.f / (1.f + __expf(-v2)), 1.f / (1.f + __expf(-v3)));
            }
    } else if (mode == 0) {
        #pragma unroll
        for (int mi = 0; mi < 4; mi++)
            #pragma unroll
            for (int ni = 0; ni < 4; ni++) {
                int r = n0 + wm + mi * 16 + g;
                int col = d0 + wn + ni * 8 + t4 * 2;
                *(uint32_t*)&g_kb[(size_t)r * DD + col] =
                    pack_h2(acc[mi][ni][0] > 0.5f ? 1.0f : 0.0f,
                            acc[mi][ni][1] > 0.5f ? 1.0f : 0.0f);
                *(uint32_t*)&g_kb[(size_t)(r + 8) * DD + col] =
                    pack_h2(acc[mi][ni][2] > 0.5f ? 1.0f : 0.0f,
                            acc[mi][ni][3] > 0.5f ? 1.0f : 0.0f);
            }
    } else {
        // V: smem transpose -> coalesced [b][h][dh][t] single-fp16 stores
        uint16_t* st = sm;
        int c = tid >> 1;
        int tstart = (tid & 1) * 64;
        int bbatch = n0 >> 11;
        int tok0 = n0 & (TT - 1);
        int gcol = d0 + c;
        int hh = gcol >> 6, dh = gcol & 63;
        size_t basei = (((size_t)(bbatch * HH + hh)) * DH + dh) * TT + tok0;
        __syncthreads();
        #pragma unroll
        for (int mi = 0; mi < 4; mi++)
            #pragma unroll
            for (int ni = 0; ni < 4; ni++) {
                int r = wm + mi * 16 + g;
                int col = wn + ni * 8 + t4 * 2;
                #pragma unroll
                for (int e = 0; e < 2; e++) {
                    f16 a = __float2half_rn(acc[mi][ni][e * 2]);
                    f16 b = __float2half_rn(acc[mi][ni][e * 2 + 1]);
                    st[(r + e * 8) * 132 + col]     = *(uint16_t*)&a;
                    st[(r + e * 8) * 132 + col + 1] = *(uint16_t*)&b;
                }
            }
        __syncthreads();
        #pragma unroll
        for (int half = 0; half < 2; half++) {
            int tb = tstart + half * 32;
            uint32_t w[16];
            #pragma unroll
            for (int j = 0; j < 16; j++) {
                uint32_t lo16 = st[(tb + 2 * j) * 132 + c];
                uint32_t hi16 = st[(tb + 2 * j + 1) * 132 + c];
                w[j] = lo16 | (hi16 << 16);
            }
            uint4* dp = (uint4*)(g_vth + basei + tb);
            dp[0] = ((uint4*)w)[0]; dp[1] = ((uint4*)w)[1];
            dp[2] = ((uint4*)w)[2]; dp[3] = ((uint4*)w)[3];
        }
    }
}

// ---------------- final output GEMM (+bias), single x single --------------------
__global__ void __launch_bounds__(256, 2) out_gemm_kernel(
        const float* __restrict__ bias, float* __restrict__ out) {
    extern __shared__ uint16_t sm[];
    int n0 = blockIdx.y * 128, d0 = blockIdx.x * 128;

    float acc[4][4][4];
    #pragma unroll
    for (int i = 0; i < 4; i++)
        #pragma unroll
        for (int j = 0; j < 4; j++)
            #pragma unroll
            for (int q = 0; q < 4; q++) acc[i][j][q] = 0.0f;

    gemm_core<0>(g_of, nullptr, g_woh, nullptr, n0, d0, sm, acc);

    int lane = threadIdx.x & 31, warp = threadIdx.x >> 5;
    int g = lane >> 2, t4 = lane & 3;
    int wm = (warp & 1) * 64, wn = (warp >> 1) * 32;

    #pragma unroll
    for (int mi = 0; mi < 4; mi++) {
        #pragma unroll
        for (int ni = 0; ni < 4; ni++) {
            int r = n0 + wm + mi * 16 + g;
            int col = d0 + wn + ni * 8 + t4 * 2;
            float b0 = bias[col], b1 = bias[col + 1];
            *(float2*)&out[(size_t)r * DD + col] =
                make_float2(acc[mi][ni][0] + b0, acc[mi][ni][1] + b1);
            *(float2*)&out[(size_t)(r + 8) * DD + col] =
                make_float2(acc[mi][ni][2] + b0, acc[mi][ni][3] + b1);
        }
    }
}

// ---------------- flash attention: fp16-acc QK, batched phases ------------------
// Max-free exp2 softmax (acc init (-4,-4) packed; uniform offset cancels in o/l).
// QK accumulates in fp16 -> D regs ARE the packed half2 scores: exp2h2 applies
// directly, zero cvt/pack ops. O and l stay fp32 (their error wouldn't cancel).
#define FSK 72
#define FLASH_SMEM (3*2*64*FSK*2)   /* 55296 B */
#define ONES_H2 0x3C003C00u
#define NEG4_H2 0xC400C400u

__global__ void __launch_bounds__(256) flash_mma_kernel(
        const f16* __restrict__ Qf, const f16* __restrict__ Kb,
        const f16* __restrict__ Vth, const float* __restrict__ Gt,
        f16* __restrict__ Of) {
    extern __shared__ uint16_t smf[];
    int tid = threadIdx.x;
    int warp = tid >> 5, lane = tid & 31;
    int g = lane >> 2, t4 = lane & 3;
    int b = blockIdx.z, h = blockIdx.y;
    int q0 = blockIdx.x * 128 + warp * 16;
    size_t baseR = (size_t)b * TT * DD + h * DH;
    size_t baseV = ((size_t)b * HH + h) * DH * TT;
    uint32_t sb = smem_u32(smf);

    int lmRow = ((lane >> 4) & 1) * 8 + (lane & 7);
    int lmCol = ((lane >> 3) & 1) * 8;

    auto stage_load = [&](int st, int kt) {
        #pragma unroll
        for (int i = 0; i < 4; i++) {
            const int arr = i >> 1;
            int rc = tid + (i & 1) * 256;
            int row = rc >> 3, c = rc & 7;
            const f16* src = (arr == 0)
                ? Kb  + baseR + (size_t)(kt * 64 + row) * DD + c * 8
                : Vth + baseV + (size_t)row * TT + kt * 64 + c * 8;
            uint32_t dst = sb + (uint32_t)((((st * 2 + arr) * 64 + row) * FSK + c * 8) * 2);
            cpa16(dst, src);
        }
        cp_commit();
    };

    // Q fragments: direct fp16 loads (pre-scaled by proj epilogue)
    uint32_t qf[4][4];
    #pragma unroll
    for (int kc = 0; kc < 4; kc++) {
        int c = kc * 16 + t4 * 2;
        #pragma unroll
        for (int half = 0; half < 2; half++) {
            int row0 = q0 + g, row1 = q0 + 8 + g;
            int cc = c + half * 8;
            qf[kc][half * 2]     = *(const uint32_t*)&Qf[baseR + (size_t)row0 * DD + cc];
            qf[kc][half * 2 + 1] = *(const uint32_t*)&Qf[baseR + (size_t)row1 * DD + cc];
        }
    }

    float o[8][4];
    #pragma unroll
    for (int i = 0; i < 8; i++)
        #pragma unroll
        for (int j = 0; j < 4; j++) o[i][j] = 0.0f;
    float ol[4];
    #pragma unroll
    for (int j = 0; j < 4; j++) ol[j] = 0.0f;

    stage_load(0, 0);
    stage_load(1, 1);
    for (int kt = 0; kt < 32; kt++) {
        if (kt == 31) cp_wait<0>(); else cp_wait<1>();
        __syncthreads();
        if (kt < 30) stage_load((kt + 2) % 3, kt + 2);

        int st3 = kt % 3;
        uint32_t sbK = sb + (uint32_t)((st3 * 2 + 0) * 64 * FSK * 2);
        uint32_t sbV = sb + (uint32_t)((st3 * 2 + 1) * 64 * FSK * 2);

        // ---- phase 1: S = Q K^T, fp16 accumulators (init (-4,-4)) ----
        uint32_t sh2[8][2];
        #pragma unroll
        for (int i = 0; i < 8; i++) { sh2[i][0] = NEG4_H2; sh2[i][1] = NEG4_H2; }
        #pragma unroll
        for (int nt2 = 0; nt2 < 4; nt2++) {
            #pragma unroll
            for (int kc = 0; kc < 4; kc++) {
                uint32_t bm[4];
                uint32_t addr = sbK + (uint32_t)(((nt2 * 16 + lmRow) * FSK + kc * 16 + lmCol) * 2);
                ldsm4(bm, addr);
                mma_f16_h2(sh2[2 * nt2],     qf[kc][0], qf[kc][1], qf[kc][2], qf[kc][3], bm[0], bm[1]);
                mma_f16_h2(sh2[2 * nt2 + 1], qf[kc][0], qf[kc][1], qf[kc][2], qf[kc][3], bm[2], bm[3]);
            }
        }

        // ---- phase 2: P = exp2(S) directly on packed half2 (no cvts) ----
        uint32_t ap[4][4];
        #pragma unroll
        for (int kc2 = 0; kc2 < 4; kc2++) {
            int ta = 2 * kc2, tb = 2 * kc2 + 1;
            ap[kc2][0] = exp2h2(sh2[ta][0]);
            ap[kc2][1] = exp2h2(sh2[ta][1]);
            ap[kc2][2] = exp2h2(sh2[tb][0]);
            ap[kc2][3] = exp2h2(sh2[tb][1]);
        }

        // ---- phase 3: O += P V (fp32 acc), l ones-MMAs riding the batch ----
        #pragma unroll
        for (int nt2 = 0; nt2 < 4; nt2++) {
            #pragma unroll
            for (int kc2 = 0; kc2 < 4; kc2++) {
                uint32_t bm[4];
                uint32_t addr = sbV + (uint32_t)(((nt2 * 16 + lmRow) * FSK + kc2 * 16 + lmCol) * 2);
                ldsm4(bm, addr);
                mma_f16(o[2 * nt2],     ap[kc2][0], ap[kc2][1], ap[kc2][2], ap[kc2][3], bm[0], bm[1]);
                mma_f16(o[2 * nt2 + 1], ap[kc2][0], ap[kc2][1], ap[kc2][2], ap[kc2][3], bm[2], bm[3]);
                if (nt2 == 0)
                    mma_f16(ol, ap[kc2][0], ap[kc2][1], ap[kc2][2], ap[kc2][3], ONES_H2, ONES_H2);
            }
        }
    }

    // l = row sums straight from the ones-MMA accumulator (no shuffles)
    float inv0 = 1.0f / ol[0], inv1 = 1.0f / ol[2];

    int row0 = q0 + g, row1 = q0 + 8 + g;
    #pragma unroll
    for (int nt = 0; nt < 8; nt++) {
        int d = nt * 8 + t4 * 2;
        size_t i0 = baseR + (size_t)row0 * DD + d;
        size_t i1 = baseR + (size_t)row1 * DD + d;
        float2 g0 = *(const float2*)&Gt[i0];
        float2 g1 = *(const float2*)&Gt[i1];
        *(uint32_t*)&Of[i0] = pack_h2(g0.x * o[nt][0] * inv0, g0.y * o[nt][1] * inv0);
        *(uint32_t*)&Of[i1] = pack_h2(g1.x * o[nt][2] * inv1, g1.y * o[nt][3] * inv1);
    }
}

// -------------------------------------------------------------------------------
extern "C" void kernel_launch(void* const* d_in, const int* in_sizes, int n_in,
                              void* d_out, int out_size) {
    const float* x   = (const float*)d_in[0];
    const int*   tok = (const int*)  d_in[1];
    const float* Wr  = (const float*)d_in[2];
    const float* Wk  = (const float*)d_in[3];
    const float* Wv  = (const float*)d_in[4];
    const float* Wo  = (const float*)d_in[5];
    const float* bo  = (const float*)d_in[6];
    const float* tmk = (const float*)d_in[7];
    const float* tmv = (const float*)d_in[8];
    const float* tmr = (const float*)d_in[9];
    float* out = (float*)d_out;

    f16 *pof, *pkb, *pvth, *pqf;
    float *pgate;
    cudaGetSymbolAddress((void**)&pof,   g_of);
    cudaGetSymbolAddress((void**)&pkb,   g_kb);
    cudaGetSymbolAddress((void**)&pvth,  g_vth);
    cudaGetSymbolAddress((void**)&pqf,   g_qf);
    cudaGetSymbolAddress((void**)&pgate, g_gate);

    cudaFuncSetAttribute(kwta_split_kernel, cudaFuncAttributeMaxDynamicSharedMemorySize, KWTA_SMEM);
    cudaFuncSetAttribute(proj_gemm_kernel,  cudaFuncAttributeMaxDynamicSharedMemorySize, GEMM_SMEM);
    cudaFuncSetAttribute(out_gemm_kernel,   cudaFuncAttributeMaxDynamicSharedMemorySize, GEMM_SMEM_S);
    cudaFuncSetAttribute(flash_mma_kernel,  cudaFuncAttributeMaxDynamicSharedMemorySize, FLASH_SMEM);

    kwta_split_kernel<<<129, 1024, KWTA_SMEM>>>(tok, Wr, Wk, Wv, Wo);
    mix_kernel<<<(NTOK * DD / 2) / 256, 256>>>(x, tmk, tmv, tmr);

    proj_gemm_kernel<<<dim3(DD / 128, NTOK / 128, 3), 256, GEMM_SMEM>>>();

    flash_mma_kernel<<<dim3(TT / 128, HH, BB), 256, FLASH_SMEM>>>(pqf, pkb, pvth, pgate, pof);

    out_gemm_kernel<<<dim3(DD / 128, NTOK / 128), 256, GEMM_SMEM_S>>>(bo, out);
}